// round 1
// baseline (speedup 1.0000x reference)
#include <cuda_runtime.h>
#include <math.h>

// Problem constants
#define BB 8
#define CC1 512
#define CC2 256
#define HH1 52
#define HH2 104

// ---- scratch (device globals; no allocations allowed) ----
__device__ float g_up1[BB*CC1*HH1*HH1];   // 11.1M
__device__ float g_r1 [BB*CC1*HH1*HH1];   // 11.1M
__device__ float g_up2[BB*CC1*HH2*HH2];   // 44.3M
__device__ float g_r2 [BB*CC2*HH2*HH2];   // 22.2M
__device__ float g_wb [BB*2305];
__device__ float g_effw[BB*256*5*9];      // [b][c2][t][tap]
__device__ float g_beta[BB*5*9];          // [b][t][tap]
__device__ float g_s1[512], g_o1[512], g_s2[256], g_o2[256];

// ---- BN folding: scale = g*rsqrt(v+eps), offset = b - m*scale ----
__global__ void bnprep_kernel(const float* __restrict__ g1,const float* __restrict__ b1,
                              const float* __restrict__ m1,const float* __restrict__ v1,
                              const float* __restrict__ g2,const float* __restrict__ b2,
                              const float* __restrict__ m2,const float* __restrict__ v2){
  int i = threadIdx.x;
  if (i < 512){ float s = g1[i]*rsqrtf(v1[i]+1e-5f); g_s1[i]=s; g_o1[i]=b1[i]-m1[i]*s; }
  if (i < 256){ float s = g2[i]*rsqrtf(v2[i]+1e-5f); g_s2[i]=s; g_o2[i]=b2[i]-m2[i]*s; }
}

// ---- bilinear 2x upsample, jax.image.resize semantics:
// out[2k]   = 0.25*in[max(k-1,0)] + 0.75*in[k]
// out[2k+1] = 0.75*in[k] + 0.25*in[min(k+1,H-1)]   (edge-renormalized == clamp)
__global__ void up2x_kernel(const float* __restrict__ in, float* __restrict__ out,
                            int NC, int Hin, int Win){
  int Hout = 2*Hin, Wout = 2*Win;
  long long total = (long long)NC*Hout*Wout;
  long long idx = (long long)blockIdx.x*blockDim.x + threadIdx.x;
  if (idx >= total) return;
  int x = (int)(idx % Wout);
  long long rr = idx / Wout;
  int y = (int)(rr % Hout);
  int c = (int)(rr / Hout);
  int ky = y>>1, kx = x>>1;
  int ya, yb, xa, xb; float wy0, wx0;
  if (y & 1){ ya=ky; yb=min(ky+1,Hin-1); wy0=0.75f; } else { ya=max(ky-1,0); yb=ky; wy0=0.25f; }
  if (x & 1){ xa=kx; xb=min(kx+1,Win-1); wx0=0.75f; } else { xa=max(kx-1,0); xb=kx; wx0=0.25f; }
  float wy1 = 1.f - wy0, wx1 = 1.f - wx0;
  const float* p = in + (long long)c*Hin*Win;
  out[idx] = wy0*(wx0*p[ya*Win+xa] + wx1*p[ya*Win+xb])
           + wy1*(wx0*p[yb*Win+xa] + wx1*p[yb*Win+xb]);
}

// ---- direct 3x3 conv (pad=1) + fused BN scale/offset + ReLU ----
// 256 threads: 128-oc x (8 rows x 16 cols) tile; 8 oc x 8 px per thread.
template<int CIN,int COUT,int HW>
__global__ __launch_bounds__(256,2)
void conv3x3_kernel(const float* __restrict__ in, const float* __restrict__ wgt,
                    const float* __restrict__ scale, const float* __restrict__ offs,
                    float* __restrict__ out){
  constexpr int TR=8, TC=16, OCT=128, CK=8;
  constexpr int CT = (HW + TC - 1)/TC;
  __shared__ float s_w[OCT*73];     // [oc][ci*9+tap], row stride 73 (conflict-free)
  __shared__ float s_in[CK*10*19];  // [ci][10 rows][19 cols] (18 used, pad 19)
  int tid = threadIdx.x;
  int tc = blockIdx.x % CT, tr = blockIdx.x / CT;
  int y0 = tr*TR, x0 = tc*TC;
  int oc0 = blockIdx.y * OCT;
  int b   = blockIdx.z;
  int pxg = tid & 15, ocg = tid >> 4;
  int r  = pxg >> 1;
  int c0 = (pxg & 1) * 8;

  float acc[8][8];
  #pragma unroll
  for (int o=0;o<8;o++)
    #pragma unroll
    for (int p=0;p<8;p++) acc[o][p]=0.f;

  for (int cb = 0; cb < CIN/CK; cb++){
    // weights: global [oc][ci][tap] contiguous 72-float runs -> smem stride 73
    for (int idx = tid; idx < OCT*CK*9; idx += 256){
      int oc  = idx / (CK*9);
      int rem = idx - oc*(CK*9);
      s_w[oc*73 + rem] = wgt[(oc0+oc)*(CIN*9) + cb*(CK*9) + rem];
    }
    // input patch (zero-padded)
    for (int idx = tid; idx < CK*10*18; idx += 256){
      int ci  = idx / 180;
      int rem = idx - ci*180;
      int ry = rem / 18, rx = rem - ry*18;
      int gy = y0 - 1 + ry, gx = x0 - 1 + rx;
      float v = 0.f;
      if (gy >= 0 && gy < HW && gx >= 0 && gx < HW)
        v = in[((b*CIN + cb*CK + ci)*HW + gy)*HW + gx];
      s_in[(ci*10+ry)*19 + rx] = v;
    }
    __syncthreads();
    #pragma unroll
    for (int ci=0;ci<CK;ci++){
      #pragma unroll
      for (int ky=0;ky<3;ky++){
        float rowv[10];
        #pragma unroll
        for (int j=0;j<10;j++) rowv[j] = s_in[(ci*10 + r + ky)*19 + c0 + j];
        #pragma unroll
        for (int kx=0;kx<3;kx++){
          float wv[8];
          #pragma unroll
          for (int o=0;o<8;o++) wv[o] = s_w[(ocg*8+o)*73 + ci*9 + ky*3 + kx];
          #pragma unroll
          for (int o=0;o<8;o++)
            #pragma unroll
            for (int p=0;p<8;p++)
              acc[o][p] = fmaf(wv[o], rowv[p+kx], acc[o][p]);
        }
      }
    }
    __syncthreads();
  }
  int y = y0 + r;
  if (y < HW){
    #pragma unroll
    for (int o=0;o<8;o++){
      int oc = oc0 + ocg*8 + o;
      float s = scale[oc], of = offs[oc];
      #pragma unroll
      for (int p=0;p<8;p++){
        int x = x0 + c0 + p;
        if (x < HW){
          float v = fmaf(acc[o][p], s, of);
          out[((b*COUT + oc)*HW + y)*HW + x] = v > 0.f ? v : 0.f;
        }
      }
    }
  }
}

// ---- wb = word @ txt_w.T + txt_b  (8 x 2305) ----
__global__ void wb_kernel(const float* __restrict__ word, const float* __restrict__ txt_w,
                          const float* __restrict__ txt_b){
  int j = blockIdx.x;                 // 0..2304
  int warp = threadIdx.x >> 5, lane = threadIdx.x & 31;  // warp = batch b
  const float* wrow = word + warp*1024;
  const float* trow = txt_w + (long long)j*1024;
  float s = 0.f;
  for (int k = lane; k < 1024; k += 32) s = fmaf(wrow[k], trow[k], s);
  #pragma unroll
  for (int off=16; off; off>>=1) s += __shfl_down_sync(0xffffffffu, s, off);
  if (lane == 0) g_wb[warp*2305 + j] = s + txt_b[j];
}

// ---- effW[b][c2][t][tap] = sum_c dyn_w[b][c][tap] * w3[t*256+c][c2]
//      beta[b][t][tap]     = sum_c dyn_w[b][c][tap] * b3[t*256+c]
__global__ void effw_kernel(const float* __restrict__ w3, const float* __restrict__ b3){
  int bid = blockIdx.x;               // b*45 + t*9 + tap
  int tap = bid % 9; int t = (bid/9) % 5; int b = bid/45;
  int tid = threadIdx.x;              // 256 = c2
  __shared__ float dw[256];
  __shared__ float red[256];
  dw[tid] = g_wb[b*2305 + tid*9 + tap];
  __syncthreads();
  float acc = 0.f;
  #pragma unroll 4
  for (int c = 0; c < 256; c++)
    acc = fmaf(dw[c], w3[(t*256 + c)*256 + tid], acc);
  g_effw[((b*256 + tid)*5 + t)*9 + tap] = acc;
  red[tid] = dw[tid] * b3[t*256 + tid];
  __syncthreads();
  for (int s=128; s; s>>=1){ if (tid < s) red[tid] += red[tid+s]; __syncthreads(); }
  if (tid == 0) g_beta[b*45 + t*9 + tap] = red[0];
}

// ---- fused (1x1 conv + dynamic 3x3 conv): 5 task outputs per batch ----
// 256 threads: 32x32 pixel tile, 4 px per thread, 5 task accumulators.
__global__ __launch_bounds__(256)
void dynconv_kernel(float* __restrict__ out){
  constexpr int HW = 104;
  __shared__ float s_in[8*34*35];
  __shared__ float s_w[8*45];       // [ci][t*9+tap]
  __shared__ float s_beta[45];
  int tid = threadIdx.x;
  int tile = blockIdx.x;            // 0..15
  int tx = tile & 3, ty = tile >> 2;
  int y0 = ty*32, x0 = tx*32;
  int b = blockIdx.y;
  if (tid < 45) s_beta[tid] = g_beta[b*45 + tid];
  int r  = tid >> 3;                // 0..31
  int c0 = (tid & 7) * 4;           // 0..28
  float acc[5][4];
  #pragma unroll
  for (int t=0;t<5;t++)
    #pragma unroll
    for (int p=0;p<4;p++) acc[t][p]=0.f;

  for (int cb = 0; cb < 32; cb++){
    for (int idx = tid; idx < 8*34*34; idx += 256){
      int ci  = idx / 1156;
      int rem = idx - ci*1156;
      int ry = rem / 34, rx = rem - ry*34;
      int gy = y0-1+ry, gx = x0-1+rx;
      float v = 0.f;
      if (gy>=0 && gy<HW && gx>=0 && gx<HW)
        v = g_r2[((b*256 + cb*8 + ci)*HW + gy)*HW + gx];
      s_in[(ci*34+ry)*35 + rx] = v;
    }
    for (int idx = tid; idx < 360; idx += 256)
      s_w[idx] = g_effw[(b*256 + cb*8)*45 + idx];
    __syncthreads();
    #pragma unroll
    for (int ci=0;ci<8;ci++){
      #pragma unroll
      for (int ky=0;ky<3;ky++){
        float rowv[6];
        #pragma unroll
        for (int j=0;j<6;j++) rowv[j] = s_in[(ci*34 + r + ky)*35 + c0 + j];
        #pragma unroll
        for (int kx=0;kx<3;kx++){
          #pragma unroll
          for (int t=0;t<5;t++){
            float wv = s_w[ci*45 + t*9 + ky*3 + kx];
            #pragma unroll
            for (int p=0;p<4;p++)
              acc[t][p] = fmaf(wv, rowv[p+kx], acc[t][p]);
          }
        }
      }
    }
    __syncthreads();
  }
  float dynb = g_wb[b*2305 + 2304];
  int y = y0 + r;
  if (y >= HW) return;
  #pragma unroll
  for (int p=0;p<4;p++){
    int x = x0 + c0 + p;
    if (x >= HW) continue;
    #pragma unroll
    for (int t=0;t<5;t++){
      float v = acc[t][p] + dynb;
      #pragma unroll
      for (int ky=0;ky<3;ky++){
        int yy = y+ky-1;
        if (yy < 0 || yy >= HW) continue;
        #pragma unroll
        for (int kx=0;kx<3;kx++){
          int xx = x+kx-1;
          if (xx < 0 || xx >= HW) continue;
          v += s_beta[t*9 + ky*3 + kx];
        }
      }
      out[((t*BB + b)*HW + y)*HW + x] = v;
    }
  }
}

extern "C" void kernel_launch(void* const* d_in, const int* in_sizes, int n_in,
                              void* d_out, int out_size){
  const float* x    = (const float*)d_in[0];
  const float* word = (const float*)d_in[1];
  const float* w1   = (const float*)d_in[2];
  const float* bn1g = (const float*)d_in[3];
  const float* bn1b = (const float*)d_in[4];
  const float* bn1m = (const float*)d_in[5];
  const float* bn1v = (const float*)d_in[6];
  const float* w2   = (const float*)d_in[7];
  const float* bn2g = (const float*)d_in[8];
  const float* bn2b = (const float*)d_in[9];
  const float* bn2m = (const float*)d_in[10];
  const float* bn2v = (const float*)d_in[11];
  const float* w3   = (const float*)d_in[12];
  const float* b3   = (const float*)d_in[13];
  const float* txtw = (const float*)d_in[14];
  const float* txtb = (const float*)d_in[15];
  float* out = (float*)d_out;

  float *up1, *r1, *up2, *r2, *s1, *o1, *s2, *o2;
  cudaGetSymbolAddress((void**)&up1, g_up1);
  cudaGetSymbolAddress((void**)&r1,  g_r1);
  cudaGetSymbolAddress((void**)&up2, g_up2);
  cudaGetSymbolAddress((void**)&r2,  g_r2);
  cudaGetSymbolAddress((void**)&s1,  g_s1);
  cudaGetSymbolAddress((void**)&o1,  g_o1);
  cudaGetSymbolAddress((void**)&s2,  g_s2);
  cudaGetSymbolAddress((void**)&o2,  g_o2);

  bnprep_kernel<<<1,512>>>(bn1g,bn1b,bn1m,bn1v,bn2g,bn2b,bn2m,bn2v);
  wb_kernel<<<2305,256>>>(word, txtw, txtb);
  effw_kernel<<<360,256>>>(w3, b3);

  {
    long long n = (long long)BB*CC1*HH1*HH1;
    up2x_kernel<<<(unsigned)((n+255)/256),256>>>(x, up1, BB*CC1, 26, 26);
  }
  conv3x3_kernel<512,512,52><<<dim3(28,4,BB),256>>>(up1, w1, s1, o1, r1);
  {
    long long n = (long long)BB*CC1*HH2*HH2;
    up2x_kernel<<<(unsigned)((n+255)/256),256>>>(r1, up2, BB*CC1, 52, 52);
  }
  conv3x3_kernel<512,256,104><<<dim3(91,2,BB),256>>>(up2, w2, s2, o2, r2);
  dynconv_kernel<<<dim3(16,BB),256>>>(out);
}